// round 10
// baseline (speedup 1.0000x reference)
#include <cuda_runtime.h>
#include <cuda_bf16.h>
#include <cstdint>

// ---------------- problem constants ----------------
#define BATCH 128
#define IN1   3072
#define HID   256
#define OUT2  10
#define NB    8
#define KSPL  (IN1*NB)        // 24576 : spline K region
#define KTOT  (KSPL + IN1)    // 27648 : + silu column region
#define CHUNK 768             // K per split
#define NSPLIT 36             // splits 0..31 coef, 32..35 silu
#define NTILE_N 8             // 8 * 32 = 256

// ---------------- GEMM tiling ----------------
#define BM 128
#define BN 32
#define BK 64
#define APITCH 72             // padded bf16 row pitch (144B) -> conflict-free frag LDS
#define NITER (CHUNK/BK)      // 12
#define SMEM_BYTES (2*BM*APITCH*2 + 2*BN*APITCH*2)  // 46080 (< 48KB, 2 CTAs/SM)

// ---------------- static scratch (no allocations allowed) ----------------
__device__ __align__(16) __nv_bfloat16 g_A[(size_t)BATCH * KTOT];          // 7.08 MB
__device__ __align__(16) float         g_P[(size_t)NSPLIT * BATCH * HID];  // 4.72 MB

// ---------------- helpers ----------------
__device__ __forceinline__ uint32_t f2bf2(float lo, float hi) {
    __nv_bfloat162 h = __floats2bfloat162_rn(lo, hi);
    return *reinterpret_cast<uint32_t*>(&h);
}

// Uniform-grid closed-form cubic B-spline (== Cox-de Boor on 12 uniform knots).
// Nonzero entries bb[i-3..i] for x in knot-interval i; all zero outside [-2.2,2.2).
__device__ __forceinline__ void bspline8_fast(float xv, float* bb) {
    float t  = (xv + 2.2f) * 2.5f;
    float fi = floorf(t);
    int   ii = (int)fi;
    float u  = t - fi;
    bool  inR = (t >= 0.0f) && (ii < 11);
    float u2 = u * u, u3 = u2 * u;
    float om = 1.0f - u;
    const float s = 1.0f / 6.0f;
    float v0 = u3 * s;                                    // piece s=0 (j == i)
    float v1 = (1.0f + 3.0f*u + 3.0f*u2 - 3.0f*u3) * s;   // piece s=1 (j == i-1)
    float v2 = (4.0f - 6.0f*u2 + 3.0f*u3) * s;            // piece s=2 (j == i-2)
    float v3 = om * om * om * s;                          // piece s=3 (j == i-3)
#pragma unroll
    for (int j = 0; j < 8; ++j) {
        int d = ii - j;
        float v = (d == 0) ? v0 : (d == 1) ? v1 : (d == 2) ? v2 : (d == 3) ? v3 : 0.0f;
        bb[j] = inR ? v : 0.0f;
    }
}

__device__ __forceinline__ void mma_bf16(float* d, const uint32_t* a, const uint32_t* b) {
    asm volatile(
        "mma.sync.aligned.m16n8k16.row.col.f32.bf16.bf16.f32 "
        "{%0,%1,%2,%3}, {%4,%5,%6,%7}, {%8,%9}, {%0,%1,%2,%3};\n"
        : "+f"(d[0]), "+f"(d[1]), "+f"(d[2]), "+f"(d[3])
        : "r"(a[0]), "r"(a[1]), "r"(a[2]), "r"(a[3]), "r"(b[0]), "r"(b[1]));
}

// ---------------- kernel 1: basis / silu -> A (bf16) ----------------
__global__ void __launch_bounds__(256) basis_kernel(const float* __restrict__ x) {
    const int i  = blockIdx.x * 256 + threadIdx.x;  // feature index
    const int bi = blockIdx.y;                      // batch index
    float xv = x[bi * IN1 + i];

    float sl = xv / (1.0f + __expf(-xv));           // silu

    float bb[8];
    bspline8_fast(xv, bb);

    __nv_bfloat16* dst = g_A + (size_t)bi * KTOT + (size_t)i * NB;
    uint4 pk;
    pk.x = f2bf2(bb[0], bb[1]);
    pk.y = f2bf2(bb[2], bb[3]);
    pk.z = f2bf2(bb[4], bb[5]);
    pk.w = f2bf2(bb[6], bb[7]);
    *reinterpret_cast<uint4*>(dst) = pk;

    g_A[(size_t)bi * KTOT + KSPL + i] = __float2bfloat16_rn(sl);
}

// ---------------- kernel 2: split-K bf16 MMA GEMM ----------------
// Partial C[b,n] over one 768-wide K chunk. B built on the fly from
// coef1*ssp1 (splits 0..31) or sb1 (splits 32..35). Partials -> g_P[split].
extern __shared__ __align__(16) __nv_bfloat16 smem_[];

__global__ void __launch_bounds__(256) gemm_kernel(const float* __restrict__ coef1,
                                                   const float* __restrict__ ssp1,
                                                   const float* __restrict__ sb1) {
    __nv_bfloat16* As = smem_;
    __nv_bfloat16* Bs = smem_ + 2 * BM * APITCH;

    const int tid  = threadIdx.x;
    const int lane = tid & 31;
    const int warp = tid >> 5;
    const int wm   = warp & 3;        // 4 warps along M (32 rows each)
    const int wn   = warp >> 2;       // 2 warps along N (16 cols each)
    const int n0   = blockIdx.x * BN;
    const int split = blockIdx.y;
    const int kg0   = split * CHUNK;
    const bool coefR = (split < 32);

    // B loader: thread -> (n row 0..31, 8-float k segment)
    const int tn  = tid >> 3;         // 0..31
    const int tkf = (tid & 7) << 3;   // 0,8,...,56

    // A loader: thread -> (row 0..127, 32-bf16 half-row), 16B cp.async x4
    const int ar = tid >> 1;
    const int ac = (tid & 1) << 5;
    const __nv_bfloat16* aSrcBase = g_A + (size_t)ar * KTOT + kg0 + ac;
    const uint32_t aDstBase =
        (uint32_t)__cvta_generic_to_shared(As) + (uint32_t)(ar * APITCH + ac) * 2;

    float4 breg[2][2];                // [prefetch set][2 x float4 = 8 floats]
    float acc[2][2][4];
#pragma unroll
    for (int mt = 0; mt < 2; ++mt)
#pragma unroll
        for (int nt = 0; nt < 2; ++nt)
#pragma unroll
            for (int q = 0; q < 4; ++q) acc[mt][nt][q] = 0.0f;

    auto ldgB = [&](int it, int set) {
        const int kg = kg0 + it * BK + tkf;
        if (coefR) {
            const float* p = coef1 + (size_t)(n0 + tn) * KSPL + kg;
            const float s  = ssp1[(n0 + tn) * IN1 + (kg >> 3)];
            float4 v0 = reinterpret_cast<const float4*>(p)[0];
            float4 v1 = reinterpret_cast<const float4*>(p)[1];
            breg[set][0] = make_float4(v0.x * s, v0.y * s, v0.z * s, v0.w * s);
            breg[set][1] = make_float4(v1.x * s, v1.y * s, v1.z * s, v1.w * s);
        } else {
            const float* p = sb1 + (size_t)(n0 + tn) * IN1 + (kg - KSPL);
            breg[set][0] = reinterpret_cast<const float4*>(p)[0];
            breg[set][1] = reinterpret_cast<const float4*>(p)[1];
        }
    };

    auto cpA = [&](int it, int bufd) {
        const __nv_bfloat16* src = aSrcBase + it * BK;
        uint32_t dst = aDstBase + (uint32_t)bufd * (BM * APITCH * 2);
#pragma unroll
        for (int j = 0; j < 4; ++j) {
            asm volatile("cp.async.cg.shared.global [%0], [%1], 16;\n"
                         :: "r"(dst + j * 16), "l"(src + j * 8) : "memory");
        }
    };

    const int fg = lane >> 2, ft = lane & 3;
    int aRow[2][2], bRow[2];
#pragma unroll
    for (int mt = 0; mt < 2; ++mt) {
        aRow[mt][0] = (wm * 32 + mt * 16 + fg) * (APITCH / 2);
        aRow[mt][1] = (wm * 32 + mt * 16 + 8 + fg) * (APITCH / 2);
    }
#pragma unroll
    for (int nt = 0; nt < 2; ++nt) bRow[nt] = (wn * 16 + nt * 8 + fg) * (APITCH / 2);

    // prologue: B prefetched 2 deep (registers), A 1 deep (smem double buffer)
    ldgB(0, 0);
    ldgB(1, 1);
    cpA(0, 0);
    asm volatile("cp.async.commit_group;\n" ::: "memory");

    for (int it = 0; it < NITER; ++it) {
        const int buf = it & 1;
        asm volatile("cp.async.wait_group 0;\n" ::: "memory");
        // stage B (set buf holds iteration it, loaded 2 iterations ago)
        {
            __nv_bfloat16* d = Bs + buf * BN * APITCH + tn * APITCH + tkf;
            uint4 u;
            u.x = f2bf2(breg[buf][0].x, breg[buf][0].y);
            u.y = f2bf2(breg[buf][0].z, breg[buf][0].w);
            u.z = f2bf2(breg[buf][1].x, breg[buf][1].y);
            u.w = f2bf2(breg[buf][1].z, breg[buf][1].w);
            *reinterpret_cast<uint4*>(d) = u;
        }
        __syncthreads();
        if (it + 1 < NITER) {
            cpA(it + 1, buf ^ 1);
            asm volatile("cp.async.commit_group;\n" ::: "memory");
        }
        if (it + 2 < NITER) ldgB(it + 2, buf);   // (it+2)&1 == buf
        // compute on current buffers
        {
            const uint32_t* A32 = reinterpret_cast<const uint32_t*>(As + buf * BM * APITCH);
            const uint32_t* B32 = reinterpret_cast<const uint32_t*>(Bs + buf * BN * APITCH);
#pragma unroll
            for (int ks = 0; ks < 4; ++ks) {
                const int kh = ks * 8;
                uint32_t af[2][4];
#pragma unroll
                for (int mt = 0; mt < 2; ++mt) {
                    af[mt][0] = A32[aRow[mt][0] + kh + ft];
                    af[mt][1] = A32[aRow[mt][1] + kh + ft];
                    af[mt][2] = A32[aRow[mt][0] + kh + 4 + ft];
                    af[mt][3] = A32[aRow[mt][1] + kh + 4 + ft];
                }
                uint32_t bfr[2][2];
#pragma unroll
                for (int nt = 0; nt < 2; ++nt) {
                    bfr[nt][0] = B32[bRow[nt] + kh + ft];
                    bfr[nt][1] = B32[bRow[nt] + kh + 4 + ft];
                }
#pragma unroll
                for (int mt = 0; mt < 2; ++mt)
#pragma unroll
                    for (int nt = 0; nt < 2; ++nt)
                        mma_bf16(acc[mt][nt], af[mt], bfr[nt]);
            }
        }
    }

    // epilogue: deterministic partial store
    float* Pp = g_P + (size_t)split * BATCH * HID;
#pragma unroll
    for (int mt = 0; mt < 2; ++mt) {
#pragma unroll
        for (int nt = 0; nt < 2; ++nt) {
            int row = wm * 32 + mt * 16 + fg;
            int col = n0 + wn * 16 + nt * 8 + ft * 2;
            float2 v01 = make_float2(acc[mt][nt][0], acc[mt][nt][1]);
            float2 v23 = make_float2(acc[mt][nt][2], acc[mt][nt][3]);
            *reinterpret_cast<float2*>(&Pp[row * HID + col]) = v01;
            *reinterpret_cast<float2*>(&Pp[(row + 8) * HID + col]) = v23;
        }
    }
}

// ---------------- kernel 3: reduce partials, selu, full layer 2 ----------------
__global__ void __launch_bounds__(256) layer2_kernel(const float* __restrict__ coef2,
                                                     const float* __restrict__ sb2,
                                                     const float* __restrict__ ssp2,
                                                     float* __restrict__ out) {
    const int b = blockIdx.x;     // 0..127
    const int i = threadIdx.x;    // 0..255  (hidden unit)

    // full unroll -> 36 independent front-batched loads (MLP ~36)
    float part[NSPLIT];
#pragma unroll
    for (int s = 0; s < NSPLIT; ++s)
        part[s] = g_P[((size_t)s * BATCH + b) * HID + i];
    float hv = 0.0f;
#pragma unroll
    for (int s = 0; s < NSPLIT; ++s) hv += part[s];

    // selu (jax defaults)
    const float SC = 1.0507009873554805f, AL = 1.6732632423543772f;
    float a = (hv > 0.0f) ? SC * hv : SC * (AL * expm1f(hv));

    float sl = a / (1.0f + __expf(-a));   // silu

    float bb[8];
    bspline8_fast(a, bb);

    float contrib[OUT2];
#pragma unroll
    for (int o = 0; o < OUT2; ++o) {
        const float* c = coef2 + ((size_t)o * HID + i) * NB;
        float dot = 0.0f;
#pragma unroll
        for (int g = 0; g < NB; ++g) dot += bb[g] * c[g];
        contrib[o] = sb2[o * HID + i] * sl + ssp2[o * HID + i] * dot;
    }

    __shared__ float red[OUT2][HID];
#pragma unroll
    for (int o = 0; o < OUT2; ++o) red[o][i] = contrib[o];
    __syncthreads();
    for (int st = HID / 2; st > 0; st >>= 1) {
        if (i < st) {
#pragma unroll
            for (int o = 0; o < OUT2; ++o) red[o][i] += red[o][i + st];
        }
        __syncthreads();
    }
    if (i < OUT2) out[b * OUT2 + i] = red[i][0];
}

// ---------------- launch ----------------
extern "C" void kernel_launch(void* const* d_in, const int* in_sizes, int n_in,
                              void* d_out, int out_size) {
    const float* x     = (const float*)d_in[0];
    const float* coef1 = (const float*)d_in[1];
    const float* sb1   = (const float*)d_in[2];
    const float* ssp1  = (const float*)d_in[3];
    const float* coef2 = (const float*)d_in[4];
    const float* sb2   = (const float*)d_in[5];
    const float* ssp2  = (const float*)d_in[6];
    float* out = (float*)d_out;

    basis_kernel<<<dim3(IN1 / 256, BATCH), 256>>>(x);
    gemm_kernel<<<dim3(NTILE_N, NSPLIT), 256, SMEM_BYTES>>>(coef1, ssp1, sb1);
    layer2_kernel<<<BATCH, 256>>>(coef2, sb2, ssp2, out);
}